// round 16
// baseline (speedup 1.0000x reference)
#include <cuda_runtime.h>
#include <cuda_fp16.h>
#include <cstdint>

#define BATCH 2
#define SEQ   4096
#define DIM   512
#define NH    8
#define HD    64
#define MROWS (BATCH*SEQ)
#define PADH  72    // K rows: halves per row; word stride 36 -> banks 4g conflict-free

// Scratch (allocation-free rule: __device__ globals)
__device__ __half g_xh [MROWS*DIM];        // x in fp16
__device__ __half g_Wh [4*DIM*DIM];        // Wq,Wk,Wv,Wo in fp16
__device__ __half g_Q  [BATCH*NH*SEQ*HD];  // [B,H,S,Hd], pre-scaled by 0.125*log2e
__device__ __half g_K  [BATCH*NH*SEQ*HD];  // [B,H,S,Hd]
__device__ __half g_Vt [BATCH*NH*HD*SEQ];  // [B,H,Hd,S] transposed
__device__ __half g_AOh[BATCH*SEQ*DIM];    // attention out, [B,S,D], fp16

// ===========================================================================
// helpers
// ===========================================================================
__device__ __forceinline__ uint32_t s2u(const void* p) {
    uint32_t a;
    asm("{ .reg .u64 t; cvta.to.shared.u64 t, %1; cvt.u32.u64 %0, t; }"
        : "=r"(a) : "l"(p));
    return a;
}
__device__ __forceinline__ unsigned pack2(float lo, float hi) {
    unsigned d;
    asm("cvt.rn.f16x2.f32 %0, %1, %2;" : "=r"(d) : "f"(hi), "f"(lo));
    return d;
}
// e = 2^(x - 8) elementwise on f16x2
__device__ __forceinline__ unsigned ex2sub8(unsigned x) {
    unsigned r;
    asm("{ .reg .b32 s; sub.f16x2 s, %1, %2; ex2.approx.f16x2 %0, s; }"
        : "=r"(r) : "r"(x), "r"(0x48004800u));
    return r;
}
// D += A(16x16) * B(16x8), fp16 in, fp32 accum
__device__ __forceinline__ void mma16h(float* d, const unsigned* a, const unsigned* b) {
    asm("mma.sync.aligned.m16n8k16.row.col.f32.f16.f16.f32 "
        "{%0,%1,%2,%3}, {%4,%5,%6,%7}, {%8,%9}, {%0,%1,%2,%3};"
        : "+f"(d[0]), "+f"(d[1]), "+f"(d[2]), "+f"(d[3])
        : "r"(a[0]), "r"(a[1]), "r"(a[2]), "r"(a[3]), "r"(b[0]), "r"(b[1]));
}
__device__ __forceinline__ void ldsm4(unsigned* r, uint32_t a) {
    asm volatile("ldmatrix.sync.aligned.m8n8.x4.shared.b16 {%0,%1,%2,%3}, [%4];"
                 : "=r"(r[0]), "=r"(r[1]), "=r"(r[2]), "=r"(r[3]) : "r"(a));
}
__device__ __forceinline__ void cpa16(uint32_t dst, const void* src) {
    asm volatile("cp.async.cg.shared.global [%0], [%1], 16;"
                 :: "r"(dst), "l"(src) : "memory");
}
#define CP_COMMIT() asm volatile("cp.async.commit_group;" ::: "memory")
#define CP_WAIT(n)  asm volatile("cp.async.wait_group %0;" :: "n"(n) : "memory")

// Swizzled tile (GEMM): rows of 64 halves (128B); 16B chunks.
__device__ __forceinline__ uint32_t swz(int r, int c) {
    return (uint32_t)(r*128 + (((c ^ (r & 7))) << 4));
}

// ===========================================================================
// fp32 -> fp16 pre-conversion of x and the 4 weight matrices
// ===========================================================================
__global__ __launch_bounds__(256) void to_half(
    const float* __restrict__ x,  const float* __restrict__ Wq,
    const float* __restrict__ Wk, const float* __restrict__ Wv,
    const float* __restrict__ Wo)
{
    const int i4 = blockIdx.x * 256 + threadIdx.x;   // index in float4 units
    const int NX = MROWS*DIM/4, NW = DIM*DIM/4;
    const float* src;
    __half* dst;
    int off;
    if (i4 < NX)                { src = x;  dst = g_xh;             off = i4; }
    else if (i4 < NX + NW)      { src = Wq; dst = g_Wh;             off = i4 - NX; }
    else if (i4 < NX + 2*NW)    { src = Wk; dst = g_Wh + DIM*DIM;   off = i4 - NX - NW; }
    else if (i4 < NX + 3*NW)    { src = Wv; dst = g_Wh + 2*DIM*DIM; off = i4 - NX - 2*NW; }
    else                        { src = Wo; dst = g_Wh + 3*DIM*DIM; off = i4 - NX - 3*NW; }
    float4 v = *(const float4*)(src + 4*(size_t)off);
    *(uint2*)(dst + 4*(size_t)off) = make_uint2(pack2(v.x, v.y), pack2(v.z, v.w));
}

// ===========================================================================
// GEMM (R10 verbatim, (128,3)): fp16, cp.async double-buffered, ldmatrix.
// which=0 (fused QKV): grid (24,64). which=1 (output proj): grid (8,64).
// ===========================================================================
#define ATB (128*128)                 // 16384 B per A slab
#define WTB (64*128)                  // 8192 B per W slab
#define GEMM_SMEM (2*ATB + 2*WTB)     // 49152 B

__global__ __launch_bounds__(128, 3) void gemm_h(
    const float* __restrict__ bq, const float* __restrict__ bk,
    const float* __restrict__ bv, const float* __restrict__ bo,
    float* __restrict__ out_ext, int which)
{
    extern __shared__ __align__(16) char smc[];
    const uint32_t sb = s2u(smc);

    const int pm   = which ? 3 : (blockIdx.x >> 3);
    const int head = which ? (int)blockIdx.x : (int)(blockIdx.x & 7);
    const int n0   = head * 64;
    const int m0   = blockIdx.y * 128;

    const __half* A = which ? g_AOh : g_xh;
    const __half* W = g_Wh + (size_t)pm * DIM * DIM + (size_t)n0 * DIM;
    const float* bias = (pm == 0) ? bq : (pm == 1) ? bk : (pm == 2) ? bv : bo;

    const int tid  = threadIdx.x;
    const int lane = tid & 31;
    const int w    = tid >> 5;
    const int g    = lane >> 2;
    const int t    = lane & 3;
    const int lrow = lane & 7;
    const int mid  = lane >> 3;

    // stage slab 0
    #pragma unroll
    for (int p = 0; p < 8; ++p) {
        int idx = p*128 + tid;
        int r = idx >> 3, c = idx & 7;
        cpa16(sb + swz(r, c), A + (size_t)(m0 + r)*DIM + c*8);
    }
    #pragma unroll
    for (int p = 0; p < 4; ++p) {
        int idx = p*128 + tid;
        int r = idx >> 3, c = idx & 7;
        cpa16(sb + 2*ATB + swz(r, c), W + (size_t)r*DIM + c*8);
    }
    CP_COMMIT();

    float acc[2][8][4] = {};

    for (int s8 = 0; s8 < 8; ++s8) {
        const int buf = s8 & 1;
        if (s8 + 1 < 8) {
            const int nb = buf ^ 1;
            const int kk = (s8 + 1) * 64;
            #pragma unroll
            for (int p = 0; p < 8; ++p) {
                int idx = p*128 + tid;
                int r = idx >> 3, c = idx & 7;
                cpa16(sb + nb*ATB + swz(r, c), A + (size_t)(m0 + r)*DIM + kk + c*8);
            }
            #pragma unroll
            for (int p = 0; p < 4; ++p) {
                int idx = p*128 + tid;
                int r = idx >> 3, c = idx & 7;
                cpa16(sb + 2*ATB + nb*WTB + swz(r, c), W + (size_t)r*DIM + kk + c*8);
            }
            CP_COMMIT();
            CP_WAIT(1);
        } else {
            CP_WAIT(0);
        }
        __syncthreads();

        unsigned af[2][4][4];
        {
            const uint32_t abase = sb + buf*ATB
                + (uint32_t)(32*w + ((mid & 1) << 3) + lrow)*128;
            #pragma unroll
            for (int h = 0; h < 2; ++h)
                #pragma unroll
                for (int s = 0; s < 4; ++s)
                    ldsm4(af[h][s], abase + h*2048
                          + (((2*s + (mid >> 1)) ^ lrow) << 4));
        }
        const uint32_t wbase = sb + 2*ATB + buf*WTB + lrow*128 + ((mid ^ lrow) << 4);
        #pragma unroll
        for (int j = 0; j < 8; ++j) {
            unsigned bb[8];
            ldsm4(bb,     wbase + j*1024);
            ldsm4(bb + 4, (wbase + j*1024) ^ 64);
            #pragma unroll
            for (int s = 0; s < 4; ++s) {
                mma16h(acc[0][j], af[0][s], bb + 2*s);
                mma16h(acc[1][j], af[1][s], bb + 2*s);
            }
        }
        __syncthreads();
    }

    float bvv[8][2];
    #pragma unroll
    for (int j = 0; j < 8; ++j) {
        bvv[j][0] = bias[n0 + 8*j + 2*t];
        bvv[j][1] = bias[n0 + 8*j + 2*t + 1];
    }
    const float QSC = 0.125f * 1.4426950408889634f;

    #pragma unroll
    for (int h = 0; h < 2; ++h) {
        int ra = m0 + 32*w + 16*h + g;
        #pragma unroll
        for (int half = 0; half < 2; ++half) {
            int m = ra + 8*half;
            int cp = half << 1;
            if (pm <= 1) {
                int b = m >> 12;
                int s = m & (SEQ - 1);
                __half* out = (pm == 0) ? g_Q : g_K;
                __half* dst = out + ((size_t)(b*NH + head)*SEQ + s) * HD;
                float sc = (pm == 0) ? QSC : 1.0f;
                #pragma unroll
                for (int j = 0; j < 8; ++j)
                    *(__half2*)(dst + 8*j + 2*t) = __floats2half2_rn(
                        (acc[h][j][cp]   + bvv[j][0]) * sc,
                        (acc[h][j][cp+1] + bvv[j][1]) * sc);
            } else if (pm == 2) {
                int b = m >> 12;
                int s = m & (SEQ - 1);
                __half* dst = g_Vt + (size_t)(b*NH + head)*HD*SEQ;
                #pragma unroll
                for (int j = 0; j < 8; ++j) {
                    int hd = 8*j + 2*t;
                    dst[(size_t)hd*SEQ + s]     = __float2half(acc[h][j][cp]   + bvv[j][0]);
                    dst[(size_t)(hd+1)*SEQ + s] = __float2half(acc[h][j][cp+1] + bvv[j][1]);
                }
            } else {
                float* dst = out_ext + (size_t)m * DIM + n0;
                #pragma unroll
                for (int j = 0; j < 8; ++j)
                    *(float2*)(dst + 8*j + 2*t) =
                        make_float2(acc[h][j][cp]   + bvv[j][0],
                                    acc[h][j][cp+1] + bvv[j][1]);
            }
        }
    }
}

// ===========================================================================
// Flash attention, KV tile 128 (32 iterations), __launch_bounds__(128,3):
// 3 CTAs/SM -> grid 512 runs in 1.15 waves (was 1.73 at 2 CTAs/SM).
// fp16 mma + f32 accum, ones-column lsum.
// 128 thr / 4 warps; warp owns 32 Q rows; CTA tile 128 rows.
// K rows: 64 halves data, stride PADH(72). V rows: hd (+8 ones), 128 keys,
// stride 136 halves (68 words -> banks 4g, conflict-free).
// ===========================================================================
#define TS     128                    // KV tile size (keys)
#define NITER  (SEQ/TS)               // 32
#define VSTRH  136                    // V row stride in halves
#define KTB    (TS*PADH*2)            // 18432 B per K buffer
#define VTB    (72*VSTRH*2)           // 19584 B per V buffer
#define SM_V   (2*KTB)
#define FSM_TOT (2*KTB + 2*VTB)       // 76032 B  (x3 CTAs = 228096 <= 233472)

__global__ __launch_bounds__(128, 3) void flash_attn()
{
    extern __shared__ __align__(16) char smem[];
    const uint32_t sb = s2u(smem);

    const int tid  = threadIdx.x;
    const int lane = tid & 31;
    const int w    = tid >> 5;
    const int g    = lane >> 2;
    const int t    = lane & 3;
    const int q0   = blockIdx.x * 128;
    const int bh   = blockIdx.y;

    const __half* Qb = g_Q  + ((size_t)bh*SEQ + q0) * HD;
    const __half* Kb = g_K  + (size_t)bh*SEQ*HD;
    const __half* Vb = g_Vt + (size_t)bh*HD*SEQ;

    // stage tile T (K: 128 rows x 64 halves; V: 64 hd rows x 128 keys)
    auto stage = [&](int T) {
        const uint32_t kd = sb + (T & 1)*KTB;
        const uint32_t vd = sb + SM_V + (T & 1)*VTB;
        const __half* Ks = Kb + (size_t)T*TS*HD;
        const __half* Vs = Vb + (size_t)T*TS;
        #pragma unroll
        for (int p = 0; p < 8; ++p) {
            int idx = p*128 + tid;
            int r = idx >> 3, c8 = (idx & 7) << 3;
            cpa16(kd + r*(PADH*2) + c8*2, Ks + (size_t)r*HD + c8);
        }
        #pragma unroll
        for (int p = 0; p < 8; ++p) {
            int idx = p*128 + tid;
            int r = idx >> 4, c16 = idx & 15;
            cpa16(vd + r*(VSTRH*2) + c16*16, Vs + (size_t)r*SEQ + c16*8);
        }
    };

    stage(0);
    CP_COMMIT();

    // Q fragments straight from gmem (persist whole kernel)
    unsigned qf[2][4][4];
    #pragma unroll
    for (int h = 0; h < 2; ++h) {
        const int r0 = 32*w + 16*h + g;
        #pragma unroll
        for (int s = 0; s < 4; ++s) {
            qf[h][s][0] = *(const unsigned*)(Qb + (size_t)r0*HD     + 16*s + 2*t);
            qf[h][s][1] = *(const unsigned*)(Qb + (size_t)(r0+8)*HD + 16*s + 2*t);
            qf[h][s][2] = *(const unsigned*)(Qb + (size_t)r0*HD     + 16*s + 8 + 2*t);
            qf[h][s][3] = *(const unsigned*)(Qb + (size_t)(r0+8)*HD + 16*s + 8 + 2*t);
        }
    }

    // ones-rows (hd 64..71) for both V buffers: row 64 = 1, rest 0
    for (int idx = tid; idx < 2*8*VSTRH; idx += 128) {
        int bsel = idx / (8*VSTRH);
        int rem  = idx % (8*VSTRH);
        int rr   = rem / VSTRH, c = rem % VSTRH;
        *((__half*)(smem + SM_V + bsel*VTB) + (64 + rr)*VSTRH + c) =
            __float2half(rr == 0 ? 1.f : 0.f);
    }
    CP_WAIT(0);
    __syncthreads();

    float O[2][9][4] = {};   // j=8 column group accumulates lsum (ones column)

    for (int T = 0; T < NITER; ++T) {
        const int buf = T & 1;
        if (T + 1 < NITER) {
            stage(T + 1);
            CP_COMMIT();
            CP_WAIT(1);
        } else {
            CP_WAIT(0);
        }
        __syncthreads();

        const unsigned* Kw = (const unsigned*)(smem + buf*KTB);
        const unsigned* Vw = (const unsigned*)(smem + SM_V + buf*VTB);

        // S = Q K^T over 128 keys (16 j-groups), p = 2^(S-8) into A-frags
        unsigned pa[2][8][4];
        #pragma unroll
        for (int j = 0; j < 16; ++j) {
            float S0[4] = {}, S1[4] = {};
            #pragma unroll
            for (int s = 0; s < 4; ++s) {
                unsigned b[2];
                b[0] = Kw[(8*j + g)*36 + 8*s + t];
                b[1] = Kw[(8*j + g)*36 + 8*s + 4 + t];
                mma16h(S0, qf[0][s], b);
                mma16h(S1, qf[1][s], b);
            }
            const int sp = j >> 1, o = (j & 1) << 1;
            pa[0][sp][o]   = ex2sub8(pack2(S0[0], S0[1]));
            pa[0][sp][o+1] = ex2sub8(pack2(S0[2], S0[3]));
            pa[1][sp][o]   = ex2sub8(pack2(S1[0], S1[1]));
            pa[1][sp][o+1] = ex2sub8(pack2(S1[2], S1[3]));
        }

        // O += P V over 128 keys (8 sp steps); 9th j-group = lsum ones column
        #pragma unroll
        for (int sp = 0; sp < 8; ++sp) {
            #pragma unroll
            for (int j = 0; j < 9; ++j) {
                unsigned b[2];
                b[0] = Vw[(8*j + g)*68 + 8*sp + t];
                b[1] = Vw[(8*j + g)*68 + 8*sp + 4 + t];
                mma16h(O[0][j], pa[0][sp], b);
                mma16h(O[1][j], pa[1][sp], b);
            }
        }
        __syncthreads();   // buffer reuse fence
    }

    // epilogue: lsum = ones-column value held by quad lane t=0; write fp16 AO
    const int b_ = bh >> 3, h_ = bh & 7;
    #pragma unroll
    for (int rr = 0; rr < 4; ++rr) {
        const int hsel = rr >> 1, cp = (rr & 1) << 1;
        const float l = __shfl_sync(0xffffffffu, O[hsel][8][cp], lane & ~3);
        const float inv = 1.0f / l;
        const int row = 32*w + 8*rr + g;
        __half* dst = g_AOh + ((size_t)(b_*SEQ + q0 + row))*DIM + h_*HD;
        #pragma unroll
        for (int j = 0; j < 8; ++j)
            *(__half2*)(dst + 8*j + 2*t) =
                __floats2half2_rn(O[hsel][j][cp]*inv, O[hsel][j][cp+1]*inv);
    }
}

// ---------------------------------------------------------------------------
extern "C" void kernel_launch(void* const* d_in, const int* in_sizes, int n_in,
                              void* d_out, int out_size)
{
    (void)in_sizes; (void)n_in; (void)out_size;
    const float* x  = (const float*)d_in[0];
    const float* Wq = (const float*)d_in[1];
    const float* bq = (const float*)d_in[2];
    const float* Wk = (const float*)d_in[3];
    const float* bk = (const float*)d_in[4];
    const float* Wv = (const float*)d_in[5];
    const float* bv = (const float*)d_in[6];
    const float* Wo = (const float*)d_in[7];
    const float* bo = (const float*)d_in[8];
    float* out = (float*)d_out;

    cudaFuncSetAttribute(gemm_h, cudaFuncAttributeMaxDynamicSharedMemorySize, GEMM_SMEM);
    cudaFuncSetAttribute(flash_attn, cudaFuncAttributeMaxDynamicSharedMemorySize, FSM_TOT);

    const int n4 = (MROWS*DIM + 4*DIM*DIM) / 4;          // float4 units
    to_half<<<n4/256, 256>>>(x, Wq, Wk, Wv, Wo);

    gemm_h<<<dim3(24, MROWS/128), 128, GEMM_SMEM>>>(bq, bk, bv, bo, nullptr, 0);
    flash_attn<<<dim3(SEQ/128, BATCH*NH), 128, FSM_TOT>>>();
    gemm_h<<<dim3(8, MROWS/128), 128, GEMM_SMEM>>>(bq, bk, bv, bo, out, 1);
}

// round 17
// speedup vs baseline: 1.0014x; 1.0014x over previous
#include <cuda_runtime.h>
#include <cuda_fp16.h>
#include <cstdint>

#define BATCH 2
#define SEQ   4096
#define DIM   512
#define NH    8
#define HD    64
#define MROWS (BATCH*SEQ)
#define PADH  72    // K rows: halves per row; word stride 36 -> banks 4g conflict-free

// Scratch (allocation-free rule: __device__ globals)
__device__ __half g_xh [MROWS*DIM];        // x in fp16
__device__ __half g_Wh [4*DIM*DIM];        // Wq,Wk,Wv,Wo in fp16
__device__ __half g_Q  [BATCH*NH*SEQ*HD];  // [B,H,S,Hd], pre-scaled by 0.125*log2e
__device__ __half g_K  [BATCH*NH*SEQ*HD];  // [B,H,S,Hd]
__device__ __half g_Vt [BATCH*NH*HD*SEQ];  // [B,H,Hd,S] transposed
__device__ __half g_AOh[BATCH*SEQ*DIM];    // attention out, [B,S,D], fp16

// ===========================================================================
// helpers
// ===========================================================================
__device__ __forceinline__ uint32_t s2u(const void* p) {
    uint32_t a;
    asm("{ .reg .u64 t; cvta.to.shared.u64 t, %1; cvt.u32.u64 %0, t; }"
        : "=r"(a) : "l"(p));
    return a;
}
__device__ __forceinline__ unsigned pack2(float lo, float hi) {
    unsigned d;
    asm("cvt.rn.f16x2.f32 %0, %1, %2;" : "=r"(d) : "f"(hi), "f"(lo));
    return d;
}
// e = 2^(x - 8) elementwise on f16x2
__device__ __forceinline__ unsigned ex2sub8(unsigned x) {
    unsigned r;
    asm("{ .reg .b32 s; sub.f16x2 s, %1, %2; ex2.approx.f16x2 %0, s; }"
        : "=r"(r) : "r"(x), "r"(0x48004800u));
    return r;
}
// D += A(16x16) * B(16x8), fp16 in, fp32 accum
__device__ __forceinline__ void mma16h(float* d, const unsigned* a, const unsigned* b) {
    asm("mma.sync.aligned.m16n8k16.row.col.f32.f16.f16.f32 "
        "{%0,%1,%2,%3}, {%4,%5,%6,%7}, {%8,%9}, {%0,%1,%2,%3};"
        : "+f"(d[0]), "+f"(d[1]), "+f"(d[2]), "+f"(d[3])
        : "r"(a[0]), "r"(a[1]), "r"(a[2]), "r"(a[3]), "r"(b[0]), "r"(b[1]));
}
__device__ __forceinline__ void ldsm4(unsigned* r, uint32_t a) {
    asm volatile("ldmatrix.sync.aligned.m8n8.x4.shared.b16 {%0,%1,%2,%3}, [%4];"
                 : "=r"(r[0]), "=r"(r[1]), "=r"(r[2]), "=r"(r[3]) : "r"(a));
}
__device__ __forceinline__ void cpa16(uint32_t dst, const void* src) {
    asm volatile("cp.async.cg.shared.global [%0], [%1], 16;"
                 :: "r"(dst), "l"(src) : "memory");
}
#define CP_COMMIT() asm volatile("cp.async.commit_group;" ::: "memory")
#define CP_WAIT(n)  asm volatile("cp.async.wait_group %0;" :: "n"(n) : "memory")

// Swizzled tile (GEMM): rows of 64 halves (128B); 16B chunks.
__device__ __forceinline__ uint32_t swz(int r, int c) {
    return (uint32_t)(r*128 + (((c ^ (r & 7))) << 4));
}

// ===========================================================================
// fp32 -> fp16 pre-conversion of x and the 4 weight matrices
// ===========================================================================
__global__ __launch_bounds__(256) void to_half(
    const float* __restrict__ x,  const float* __restrict__ Wq,
    const float* __restrict__ Wk, const float* __restrict__ Wv,
    const float* __restrict__ Wo)
{
    const int i4 = blockIdx.x * 256 + threadIdx.x;   // index in float4 units
    const int NX = MROWS*DIM/4, NW = DIM*DIM/4;
    const float* src;
    __half* dst;
    int off;
    if (i4 < NX)                { src = x;  dst = g_xh;             off = i4; }
    else if (i4 < NX + NW)      { src = Wq; dst = g_Wh;             off = i4 - NX; }
    else if (i4 < NX + 2*NW)    { src = Wk; dst = g_Wh + DIM*DIM;   off = i4 - NX - NW; }
    else if (i4 < NX + 3*NW)    { src = Wv; dst = g_Wh + 2*DIM*DIM; off = i4 - NX - 2*NW; }
    else                        { src = Wo; dst = g_Wh + 3*DIM*DIM; off = i4 - NX - 3*NW; }
    float4 v = *(const float4*)(src + 4*(size_t)off);
    *(uint2*)(dst + 4*(size_t)off) = make_uint2(pack2(v.x, v.y), pack2(v.z, v.w));
}

// ===========================================================================
// GEMM (R10 verbatim, (128,3)): fp16, cp.async double-buffered, ldmatrix.
// which=0 (fused QKV): grid (24,64). which=1 (output proj): grid (8,64).
// ===========================================================================
#define ATB (128*128)                 // 16384 B per A slab
#define WTB (64*128)                  // 8192 B per W slab
#define GEMM_SMEM (2*ATB + 2*WTB)     // 49152 B

__global__ __launch_bounds__(128, 3) void gemm_h(
    const float* __restrict__ bq, const float* __restrict__ bk,
    const float* __restrict__ bv, const float* __restrict__ bo,
    float* __restrict__ out_ext, int which)
{
    extern __shared__ __align__(16) char smc[];
    const uint32_t sb = s2u(smc);

    const int pm   = which ? 3 : (blockIdx.x >> 3);
    const int head = which ? (int)blockIdx.x : (int)(blockIdx.x & 7);
    const int n0   = head * 64;
    const int m0   = blockIdx.y * 128;

    const __half* A = which ? g_AOh : g_xh;
    const __half* W = g_Wh + (size_t)pm * DIM * DIM + (size_t)n0 * DIM;
    const float* bias = (pm == 0) ? bq : (pm == 1) ? bk : (pm == 2) ? bv : bo;

    const int tid  = threadIdx.x;
    const int lane = tid & 31;
    const int w    = tid >> 5;
    const int g    = lane >> 2;
    const int t    = lane & 3;
    const int lrow = lane & 7;
    const int mid  = lane >> 3;

    // stage slab 0
    #pragma unroll
    for (int p = 0; p < 8; ++p) {
        int idx = p*128 + tid;
        int r = idx >> 3, c = idx & 7;
        cpa16(sb + swz(r, c), A + (size_t)(m0 + r)*DIM + c*8);
    }
    #pragma unroll
    for (int p = 0; p < 4; ++p) {
        int idx = p*128 + tid;
        int r = idx >> 3, c = idx & 7;
        cpa16(sb + 2*ATB + swz(r, c), W + (size_t)r*DIM + c*8);
    }
    CP_COMMIT();

    float acc[2][8][4] = {};

    for (int s8 = 0; s8 < 8; ++s8) {
        const int buf = s8 & 1;
        if (s8 + 1 < 8) {
            const int nb = buf ^ 1;
            const int kk = (s8 + 1) * 64;
            #pragma unroll
            for (int p = 0; p < 8; ++p) {
                int idx = p*128 + tid;
                int r = idx >> 3, c = idx & 7;
                cpa16(sb + nb*ATB + swz(r, c), A + (size_t)(m0 + r)*DIM + kk + c*8);
            }
            #pragma unroll
            for (int p = 0; p < 4; ++p) {
                int idx = p*128 + tid;
                int r = idx >> 3, c = idx & 7;
                cpa16(sb + 2*ATB + nb*WTB + swz(r, c), W + (size_t)r*DIM + kk + c*8);
            }
            CP_COMMIT();
            CP_WAIT(1);
        } else {
            CP_WAIT(0);
        }
        __syncthreads();

        unsigned af[2][4][4];
        {
            const uint32_t abase = sb + buf*ATB
                + (uint32_t)(32*w + ((mid & 1) << 3) + lrow)*128;
            #pragma unroll
            for (int h = 0; h < 2; ++h)
                #pragma unroll
                for (int s = 0; s < 4; ++s)
                    ldsm4(af[h][s], abase + h*2048
                          + (((2*s + (mid >> 1)) ^ lrow) << 4));
        }
        const uint32_t wbase = sb + 2*ATB + buf*WTB + lrow*128 + ((mid ^ lrow) << 4);
        #pragma unroll
        for (int j = 0; j < 8; ++j) {
            unsigned bb[8];
            ldsm4(bb,     wbase + j*1024);
            ldsm4(bb + 4, (wbase + j*1024) ^ 64);
            #pragma unroll
            for (int s = 0; s < 4; ++s) {
                mma16h(acc[0][j], af[0][s], bb + 2*s);
                mma16h(acc[1][j], af[1][s], bb + 2*s);
            }
        }
        __syncthreads();
    }

    float bvv[8][2];
    #pragma unroll
    for (int j = 0; j < 8; ++j) {
        bvv[j][0] = bias[n0 + 8*j + 2*t];
        bvv[j][1] = bias[n0 + 8*j + 2*t + 1];
    }
    const float QSC = 0.125f * 1.4426950408889634f;

    #pragma unroll
    for (int h = 0; h < 2; ++h) {
        int ra = m0 + 32*w + 16*h + g;
        #pragma unroll
        for (int half = 0; half < 2; ++half) {
            int m = ra + 8*half;
            int cp = half << 1;
            if (pm <= 1) {
                int b = m >> 12;
                int s = m & (SEQ - 1);
                __half* out = (pm == 0) ? g_Q : g_K;
                __half* dst = out + ((size_t)(b*NH + head)*SEQ + s) * HD;
                float sc = (pm == 0) ? QSC : 1.0f;
                #pragma unroll
                for (int j = 0; j < 8; ++j)
                    *(__half2*)(dst + 8*j + 2*t) = __floats2half2_rn(
                        (acc[h][j][cp]   + bvv[j][0]) * sc,
                        (acc[h][j][cp+1] + bvv[j][1]) * sc);
            } else if (pm == 2) {
                int b = m >> 12;
                int s = m & (SEQ - 1);
                __half* dst = g_Vt + (size_t)(b*NH + head)*HD*SEQ;
                #pragma unroll
                for (int j = 0; j < 8; ++j) {
                    int hd = 8*j + 2*t;
                    dst[(size_t)hd*SEQ + s]     = __float2half(acc[h][j][cp]   + bvv[j][0]);
                    dst[(size_t)(hd+1)*SEQ + s] = __float2half(acc[h][j][cp+1] + bvv[j][1]);
                }
            } else {
                float* dst = out_ext + (size_t)m * DIM + n0;
                #pragma unroll
                for (int j = 0; j < 8; ++j)
                    *(float2*)(dst + 8*j + 2*t) =
                        make_float2(acc[h][j][cp]   + bvv[j][0],
                                    acc[h][j][cp+1] + bvv[j][1]);
            }
        }
    }
}

// ===========================================================================
// Flash attention, KV tile 128, TRIPLE-buffered K/V, ONE barrier per tile:
// stage(T+1) writes buffer (T+1)%3 while the oldest possible reader holds
// (T-1)%3 — disjoint, so the loop-end barrier is gone and warps can drift
// a phase apart (one warp's PV HMMAs cover another's exp window).
// fp16 mma + f32 accum, ones-column lsum.
// 128 thr / 4 warps; warp owns 32 Q rows; CTA tile 128 rows.
// ===========================================================================
#define TS     128                    // KV tile size (keys)
#define NITER  (SEQ/TS)               // 32
#define VSTRH  136                    // V row stride in halves
#define KTB    (TS*PADH*2)            // 18432 B per K buffer
#define VTB    (72*VSTRH*2)           // 19584 B per V buffer
#define SM_V   (3*KTB)
#define FSM_TOT (3*KTB + 3*VTB)       // 114048 B (x2 CTAs = 228096)

__global__ void flash_attn()
{
    extern __shared__ __align__(16) char smem[];
    const uint32_t sb = s2u(smem);

    const int tid  = threadIdx.x;
    const int lane = tid & 31;
    const int w    = tid >> 5;
    const int g    = lane >> 2;
    const int t    = lane & 3;
    const int q0   = blockIdx.x * 128;
    const int bh   = blockIdx.y;

    const __half* Qb = g_Q  + ((size_t)bh*SEQ + q0) * HD;
    const __half* Kb = g_K  + (size_t)bh*SEQ*HD;
    const __half* Vb = g_Vt + (size_t)bh*HD*SEQ;

    // stage tile T into buffer slot s3 (K: 128 rows x 64 halves; V: 64 hd x 128 keys)
    auto stage = [&](int T, int s3) {
        const uint32_t kd = sb + s3*KTB;
        const uint32_t vd = sb + SM_V + s3*VTB;
        const __half* Ks = Kb + (size_t)T*TS*HD;
        const __half* Vs = Vb + (size_t)T*TS;
        #pragma unroll
        for (int p = 0; p < 8; ++p) {
            int idx = p*128 + tid;
            int r = idx >> 3, c8 = (idx & 7) << 3;
            cpa16(kd + r*(PADH*2) + c8*2, Ks + (size_t)r*HD + c8);
        }
        #pragma unroll
        for (int p = 0; p < 8; ++p) {
            int idx = p*128 + tid;
            int r = idx >> 4, c16 = idx & 15;
            cpa16(vd + r*(VSTRH*2) + c16*16, Vs + (size_t)r*SEQ + c16*8);
        }
    };

    stage(0, 0);
    CP_COMMIT();

    // Q fragments straight from gmem (persist whole kernel)
    unsigned qf[2][4][4];
    #pragma unroll
    for (int h = 0; h < 2; ++h) {
        const int r0 = 32*w + 16*h + g;
        #pragma unroll
        for (int s = 0; s < 4; ++s) {
            qf[h][s][0] = *(const unsigned*)(Qb + (size_t)r0*HD     + 16*s + 2*t);
            qf[h][s][1] = *(const unsigned*)(Qb + (size_t)(r0+8)*HD + 16*s + 2*t);
            qf[h][s][2] = *(const unsigned*)(Qb + (size_t)r0*HD     + 16*s + 8 + 2*t);
            qf[h][s][3] = *(const unsigned*)(Qb + (size_t)(r0+8)*HD + 16*s + 8 + 2*t);
        }
    }

    // ones-rows (hd 64..71) for all 3 V buffers: row 64 = 1, rest 0
    for (int idx = tid; idx < 3*8*VSTRH; idx += 128) {
        int bsel = idx / (8*VSTRH);
        int rem  = idx % (8*VSTRH);
        int rr   = rem / VSTRH, c = rem % VSTRH;
        *((__half*)(smem + SM_V + bsel*VTB) + (64 + rr)*VSTRH + c) =
            __float2half(rr == 0 ? 1.f : 0.f);
    }

    float O[2][9][4] = {};   // j=8 column group accumulates lsum (ones column)

    int cur = 0;
    for (int T = 0; T < NITER; ++T) {
        const int nxt = (cur == 2) ? 0 : cur + 1;
        if (T + 1 < NITER) {
            stage(T + 1, nxt);
            CP_COMMIT();
            CP_WAIT(1);
        } else {
            CP_WAIT(0);
        }
        __syncthreads();   // cross-warp visibility of tile T staging (only barrier)

        const unsigned* Kw = (const unsigned*)(smem + cur*KTB);
        const unsigned* Vw = (const unsigned*)(smem + SM_V + cur*VTB);

        // S = Q K^T over 128 keys (16 j-groups), p = 2^(S-8) into A-frags
        unsigned pa[2][8][4];
        #pragma unroll
        for (int j = 0; j < 16; ++j) {
            float S0[4] = {}, S1[4] = {};
            #pragma unroll
            for (int s = 0; s < 4; ++s) {
                unsigned b[2];
                b[0] = Kw[(8*j + g)*36 + 8*s + t];
                b[1] = Kw[(8*j + g)*36 + 8*s + 4 + t];
                mma16h(S0, qf[0][s], b);
                mma16h(S1, qf[1][s], b);
            }
            const int sp = j >> 1, o = (j & 1) << 1;
            pa[0][sp][o]   = ex2sub8(pack2(S0[0], S0[1]));
            pa[0][sp][o+1] = ex2sub8(pack2(S0[2], S0[3]));
            pa[1][sp][o]   = ex2sub8(pack2(S1[0], S1[1]));
            pa[1][sp][o+1] = ex2sub8(pack2(S1[2], S1[3]));
        }

        // O += P V over 128 keys (8 sp steps); 9th j-group = lsum ones column
        #pragma unroll
        for (int sp = 0; sp < 8; ++sp) {
            #pragma unroll
            for (int j = 0; j < 9; ++j) {
                unsigned b[2];
                b[0] = Vw[(8*j + g)*68 + 8*sp + t];
                b[1] = Vw[(8*j + g)*68 + 8*sp + 4 + t];
                mma16h(O[0][j], pa[0][sp], b);
                mma16h(O[1][j], pa[1][sp], b);
            }
        }
        cur = nxt;
        // no loop-end barrier: triple buffering keeps writer/reader disjoint
    }

    // epilogue: lsum = ones-column value held by quad lane t=0; write fp16 AO
    const int b_ = bh >> 3, h_ = bh & 7;
    #pragma unroll
    for (int rr = 0; rr < 4; ++rr) {
        const int hsel = rr >> 1, cp = (rr & 1) << 1;
        const float l = __shfl_sync(0xffffffffu, O[hsel][8][cp], lane & ~3);
        const float inv = 1.0f / l;
        const int row = 32*w + 8*rr + g;
        __half* dst = g_AOh + ((size_t)(b_*SEQ + q0 + row))*DIM + h_*HD;
        #pragma unroll
        for (int j = 0; j < 8; ++j)
            *(__half2*)(dst + 8*j + 2*t) =
                __floats2half2_rn(O[hsel][j][cp]*inv, O[hsel][j][cp+1]*inv);
    }
}

// ---------------------------------------------------------------------------
extern "C" void kernel_launch(void* const* d_in, const int* in_sizes, int n_in,
                              void* d_out, int out_size)
{
    (void)in_sizes; (void)n_in; (void)out_size;
    const float* x  = (const float*)d_in[0];
    const float* Wq = (const float*)d_in[1];
    const float* bq = (const float*)d_in[2];
    const float* Wk = (const float*)d_in[3];
    const float* bk = (const float*)d_in[4];
    const float* Wv = (const float*)d_in[5];
    const float* bv = (const float*)d_in[6];
    const float* Wo = (const float*)d_in[7];
    const float* bo = (const float*)d_in[8];
    float* out = (float*)d_out;

    cudaFuncSetAttribute(gemm_h, cudaFuncAttributeMaxDynamicSharedMemorySize, GEMM_SMEM);
    cudaFuncSetAttribute(flash_attn, cudaFuncAttributeMaxDynamicSharedMemorySize, FSM_TOT);

    const int n4 = (MROWS*DIM + 4*DIM*DIM) / 4;          // float4 units
    to_half<<<n4/256, 256>>>(x, Wq, Wk, Wv, Wo);

    gemm_h<<<dim3(24, MROWS/128), 128, GEMM_SMEM>>>(bq, bk, bv, bo, nullptr, 0);
    flash_attn<<<dim3(SEQ/128, BATCH*NH), 128, FSM_TOT>>>();
    gemm_h<<<dim3(8, MROWS/128), 128, GEMM_SMEM>>>(bq, bk, bv, bo, out, 1);
}